// round 3
// baseline (speedup 1.0000x reference)
#include <cuda_runtime.h>
#include <cuda_bf16.h>

// DurationCalculator:
//   weights_argmax[b,y] = duration[b,y] + (y < output_length[b] ? 0 : -10000)
//   durations[b,x]      = count over y of (weights_argmax[b,y] == x), 0 <= x < X
// Output (float32): [ weights_argmax (B*Y) | durations (B*X) ]

#ifndef MASK_PENALTY
#define MASK_PENALTY (-10000)
#endif

__global__ void __launch_bounds__(512, 2)
duration_calc_kernel(const int* __restrict__ duration,
                     const int* __restrict__ output_length,
                     float* __restrict__ w_out,
                     float* __restrict__ h_out,
                     int Y, int X)
{
    extern __shared__ int hist[];  // X bins
    const int b   = blockIdx.x;
    const int tid = threadIdx.x;
    const int nt  = blockDim.x;

    for (int i = tid; i < X; i += nt) hist[i] = 0;
    __syncthreads();

    const int L = output_length[b];

    const int4* __restrict__ dur4 = reinterpret_cast<const int4*>(duration + (size_t)b * Y);
    float4* __restrict__ w4       = reinterpret_cast<float4*>(w_out + (size_t)b * Y);
    const int n4 = Y >> 2;

    for (int i = tid; i < n4; i += nt) {
        const int y = i << 2;
        int4 d = dur4[i];
        int wx = d.x + ((y + 0) < L ? 0 : MASK_PENALTY);
        int wy = d.y + ((y + 1) < L ? 0 : MASK_PENALTY);
        int wz = d.z + ((y + 2) < L ? 0 : MASK_PENALTY);
        int ww = d.w + ((y + 3) < L ? 0 : MASK_PENALTY);
        float4 w;
        w.x = (float)wx; w.y = (float)wy; w.z = (float)wz; w.w = (float)ww;
        w4[i] = w;
        // unsigned compare folds (w >= 0 && w < X); masked entries are negative.
        if ((unsigned)wx < (unsigned)X) atomicAdd(&hist[wx], 1);
        if ((unsigned)wy < (unsigned)X) atomicAdd(&hist[wy], 1);
        if ((unsigned)wz < (unsigned)X) atomicAdd(&hist[wz], 1);
        if ((unsigned)ww < (unsigned)X) atomicAdd(&hist[ww], 1);
    }

    // tail (Y not multiple of 4) — defensive, no-op for Y=4096
    for (int y = (n4 << 2) + tid; y < Y; y += nt) {
        int w = duration[(size_t)b * Y + y] + (y < L ? 0 : MASK_PENALTY);
        w_out[(size_t)b * Y + y] = (float)w;
        if ((unsigned)w < (unsigned)X) atomicAdd(&hist[w], 1);
    }

    __syncthreads();

    float* __restrict__ hrow = h_out + (size_t)b * X;
    if ((X & 3) == 0) {
        float4* __restrict__ hrow4 = reinterpret_cast<float4*>(hrow);
        const int hx4 = X >> 2;
        for (int i = tid; i < hx4; i += nt) {
            float4 v;
            v.x = (float)hist[(i << 2) + 0];
            v.y = (float)hist[(i << 2) + 1];
            v.z = (float)hist[(i << 2) + 2];
            v.w = (float)hist[(i << 2) + 3];
            hrow4[i] = v;
        }
    } else {
        for (int i = tid; i < X; i += nt) hrow[i] = (float)hist[i];
    }
}

extern "C" void kernel_launch(void* const* d_in, const int* in_sizes, int n_in,
                              void* d_out, int out_size)
{
    const int* duration      = (const int*)d_in[0];
    const int* output_length = (const int*)d_in[1];

    const int B = in_sizes[1];          // 256
    const int Y = in_sizes[0] / B;      // 4096
    const int X = out_size / B - Y;     // 1024

    float* w_out = (float*)d_out;                   // weights_argmax: B*Y
    float* h_out = (float*)d_out + (size_t)B * Y;   // durations:      B*X

    const int threads = 512;
    const size_t smem = (size_t)X * sizeof(int);
    duration_calc_kernel<<<B, threads, smem>>>(duration, output_length,
                                               w_out, h_out, Y, X);
}

// round 5
// speedup vs baseline: 1.1814x; 1.1814x over previous
#include <cuda_runtime.h>
#include <cuda_bf16.h>

// DurationCalculator:
//   weights_argmax[b,y] = duration[b,y] + (y < output_length[b] ? 0 : -10000)
//   durations[b,x]      = count over y of (weights_argmax[b,y] == x), 0 <= x < X
// Output (float32): [ weights_argmax (B*Y) | durations (B*X) ]
//
// One CTA per batch row. 256 threads, 16 elems/thread, 4 front-batched
// LDG.128 per thread for MLP, shared 4KiB histogram, single-wave residency.

#ifndef MASK_PENALTY
#define MASK_PENALTY (-10000)
#endif

__global__ void __launch_bounds__(256, 4)
duration_calc_kernel(const int* __restrict__ duration,
                     const int* __restrict__ output_length,
                     float* __restrict__ w_out,
                     float* __restrict__ h_out,
                     int Y, int X)
{
    extern __shared__ int hist[];  // X bins
    const int b   = blockIdx.x;
    const int tid = threadIdx.x;
    const int nt  = blockDim.x;   // 256

    for (int i = tid; i < X; i += nt) hist[i] = 0;
    __syncthreads();

    const int L = output_length[b];

    const int4* __restrict__ dur4 = reinterpret_cast<const int4*>(duration + (size_t)b * Y);
    float4* __restrict__ w4       = reinterpret_cast<float4*>(w_out + (size_t)b * Y);
    const int n4 = Y >> 2;        // 1024 for Y=4096

    // Main loop: each iteration covers 4*nt int4s; 4 loads batched up front.
    for (int base = tid; base < n4; base += nt * 4) {
        const int i0 = base;
        const int i1 = base + nt;
        const int i2 = base + nt * 2;
        const int i3 = base + nt * 3;
        const bool p1 = i1 < n4, p2 = i2 < n4, p3 = i3 < n4;

        // Front-batched loads (MLP = 4)
        int4 d0 = dur4[i0];
        int4 d1 = p1 ? dur4[i1] : make_int4(0, 0, 0, 0);
        int4 d2 = p2 ? dur4[i2] : make_int4(0, 0, 0, 0);
        int4 d3 = p3 ? dur4[i3] : make_int4(0, 0, 0, 0);

        #define PROC(dd, ii, pp)                                               \
        do {                                                                   \
            if (pp) {                                                          \
                const int y = (ii) << 2;                                       \
                int wx = dd.x + ((y + 0) < L ? 0 : MASK_PENALTY);              \
                int wy = dd.y + ((y + 1) < L ? 0 : MASK_PENALTY);              \
                int wz = dd.z + ((y + 2) < L ? 0 : MASK_PENALTY);              \
                int ww = dd.w + ((y + 3) < L ? 0 : MASK_PENALTY);              \
                float4 w;                                                      \
                w.x = (float)wx; w.y = (float)wy;                              \
                w.z = (float)wz; w.w = (float)ww;                              \
                w4[ii] = w;                                                    \
                if ((unsigned)wx < (unsigned)X) atomicAdd(&hist[wx], 1);       \
                if ((unsigned)wy < (unsigned)X) atomicAdd(&hist[wy], 1);       \
                if ((unsigned)wz < (unsigned)X) atomicAdd(&hist[wz], 1);       \
                if ((unsigned)ww < (unsigned)X) atomicAdd(&hist[ww], 1);       \
            }                                                                  \
        } while (0)

        PROC(d0, i0, true);
        PROC(d1, i1, p1);
        PROC(d2, i2, p2);
        PROC(d3, i3, p3);
        #undef PROC
    }

    // Scalar tail for Y not a multiple of 4 (no-op for Y=4096)
    for (int y = (n4 << 2) + tid; y < Y; y += nt) {
        int w = duration[(size_t)b * Y + y] + (y < L ? 0 : MASK_PENALTY);
        w_out[(size_t)b * Y + y] = (float)w;
        if ((unsigned)w < (unsigned)X) atomicAdd(&hist[w], 1);
    }

    __syncthreads();

    // Write histogram as float
    float* __restrict__ hrow = h_out + (size_t)b * X;
    if ((X & 3) == 0) {
        float4* __restrict__ hrow4 = reinterpret_cast<float4*>(hrow);
        const int hx4 = X >> 2;
        for (int i = tid; i < hx4; i += nt) {
            float4 v;
            v.x = (float)hist[(i << 2) + 0];
            v.y = (float)hist[(i << 2) + 1];
            v.z = (float)hist[(i << 2) + 2];
            v.w = (float)hist[(i << 2) + 3];
            hrow4[i] = v;
        }
    } else {
        for (int i = tid; i < X; i += nt) hrow[i] = (float)hist[i];
    }
}

extern "C" void kernel_launch(void* const* d_in, const int* in_sizes, int n_in,
                              void* d_out, int out_size)
{
    const int* duration      = (const int*)d_in[0];
    const int* output_length = (const int*)d_in[1];

    const int B = in_sizes[1];          // 256
    const int Y = in_sizes[0] / B;      // 4096
    const int X = out_size / B - Y;     // 1024

    float* w_out = (float*)d_out;                   // weights_argmax: B*Y
    float* h_out = (float*)d_out + (size_t)B * Y;   // durations:      B*X

    const int threads = 256;
    const size_t smem = (size_t)X * sizeof(int);
    duration_calc_kernel<<<B, threads, smem>>>(duration, output_length,
                                               w_out, h_out, Y, X);
}